// round 13
// baseline (speedup 1.0000x reference)
#include <cuda_runtime.h>
#include <cuda_bf16.h>
#include <cstdint>

// Problem constants (fixed by the reference)
namespace cfg {
constexpr int B  = 8;
constexpr int N  = 1024;
constexpr int D  = 512;
constexpr int H  = 8;
constexpr int DK = 64;
constexpr int HD = 512;   // H*DK
constexpr int M  = B * N; // 8192 rows
constexpr size_t MD = (size_t)M * D;
}
using namespace cfg;

// Scratch (no cudaMalloc allowed) — bf16 hi/lo pairs carry the data
__device__ __align__(16) __nv_bfloat16 g_xh[3 * MD];
__device__ __align__(16) __nv_bfloat16 g_xl[3 * MD];
__device__ __align__(16) __nv_bfloat16 g_wth[4 * 512 * 512];  // W^T hi (q,k,v,o)
__device__ __align__(16) __nv_bfloat16 g_wtl[4 * 512 * 512];
__device__ __align__(16) __nv_bfloat16 g_qh[MD], g_ql[MD];    // [b,h,n,dk], prescaled 1/8
__device__ __align__(16) __nv_bfloat16 g_kh[MD], g_kl[MD];
__device__ __align__(16) __nv_bfloat16 g_vh[MD], g_vl[MD];
__device__ __align__(16) __nv_bfloat16 g_atth[MD], g_attl[MD];
__device__ __align__(16) float g_y[MD];

// ===========================================================================
// sm_80-level tensor-core helpers (valid on sm_100 target; validated in R7)
// ===========================================================================
__device__ __forceinline__ uint32_t smem_u32(const void* p) {
    uint32_t a;
    asm("{ .reg .u64 t; cvta.to.shared.u64 t, %1; cvt.u32.u64 %0, t; }" : "=r"(a) : "l"(p));
    return a;
}
__device__ __forceinline__ void ldsm_x4(uint32_t r[4], uint32_t addr) {
    asm volatile("ldmatrix.sync.aligned.m8n8.x4.shared.b16 {%0,%1,%2,%3}, [%4];"
                 : "=r"(r[0]), "=r"(r[1]), "=r"(r[2]), "=r"(r[3]) : "r"(addr));
}
__device__ __forceinline__ void mma_bf16(float c[4], const uint32_t a[4],
                                         uint32_t b0, uint32_t b1) {
    asm volatile(
        "mma.sync.aligned.m16n8k16.row.col.f32.bf16.bf16.f32 "
        "{%0,%1,%2,%3}, {%4,%5,%6,%7}, {%8,%9}, {%0,%1,%2,%3};"
        : "+f"(c[0]), "+f"(c[1]), "+f"(c[2]), "+f"(c[3])
        : "r"(a[0]), "r"(a[1]), "r"(a[2]), "r"(a[3]), "r"(b0), "r"(b1));
}
// split fp32 pair -> (hi bf16x2, lo bf16x2); element 0 in low half
__device__ __forceinline__ void split_pack(float a, float b, uint32_t& hi, uint32_t& lo) {
    __nv_bfloat16 ah = __float2bfloat16(a);
    __nv_bfloat16 bh = __float2bfloat16(b);
    __nv_bfloat16 al = __float2bfloat16(a - __bfloat162float(ah));
    __nv_bfloat16 bl = __float2bfloat16(b - __bfloat162float(bh));
    __nv_bfloat162 h2(ah, bh), l2(al, bl);
    hi = *(uint32_t*)&h2;
    lo = *(uint32_t*)&l2;
}

// ---------------------------------------------------------------------------
// Prep 1: X (queries/keys/values) fp32 -> hi/lo bf16, elementwise.
// ---------------------------------------------------------------------------
__global__ __launch_bounds__(256) void convert_x_kernel(
    const float* __restrict__ q, const float* __restrict__ k, const float* __restrict__ v)
{
    const int z = blockIdx.y;
    const float* src = (z == 0) ? q : (z == 1) ? k : v;
    const size_t idx = ((size_t)blockIdx.x * 256 + threadIdx.x) * 4;
    const float4 val = *(const float4*)&src[idx];
    uint32_t h0, l0, h1, l1;
    split_pack(val.x, val.y, h0, l0);
    split_pack(val.z, val.w, h1, l1);
    const size_t o = (size_t)z * MD + idx;
    *(uint2*)&g_xh[o] = make_uint2(h0, h1);
    *(uint2*)&g_xl[o] = make_uint2(l0, l1);
}

// ---------------------------------------------------------------------------
// Prep 2: W [k][n] fp32 -> W^T [n][k] hi/lo bf16 (tiled transpose).
// ---------------------------------------------------------------------------
__global__ __launch_bounds__(256) void transpose_w_kernel(
    const float* __restrict__ Wq, const float* __restrict__ Wk,
    const float* __restrict__ Wv, const float* __restrict__ Wo)
{
    __shared__ float tile[64][65];
    const int t = threadIdx.x;
    const int mat = blockIdx.z;
    const float* W = (mat == 0) ? Wq : (mat == 1) ? Wk : (mat == 2) ? Wv : Wo;
    const int r0 = blockIdx.y * 64;   // k block
    const int c0 = blockIdx.x * 64;   // n block
#pragma unroll
    for (int u = 0; u < 16; u++) {
        const int idx = t + u * 256;
        tile[idx >> 6][idx & 63] = W[(size_t)(r0 + (idx >> 6)) * 512 + c0 + (idx & 63)];
    }
    __syncthreads();
#pragma unroll
    for (int u = 0; u < 8; u++) {
        const int idx = t + u * 256;
        const int nl = idx >> 5;
        const int k0 = (idx & 31) * 2;
        uint32_t hi, lo;
        split_pack(tile[k0][nl], tile[k0 + 1][nl], hi, lo);
        const size_t o = (size_t)mat * 262144 + (size_t)(c0 + nl) * 512 + r0 + k0;
        *(uint32_t*)&g_wth[o] = hi;
        *(uint32_t*)&g_wtl[o] = lo;
    }
}

// ---------------------------------------------------------------------------
// Kernel 1: QKV projections via mma.sync, compensated bf16 (3-term).
// 128x128 tile, kstep 32, 8 warps as 4(m) x 2(n); warp tile 32x64.
// Epilogue: +bias (Q also x1/8), split hi/lo, store [b,h,n,dk] bf16.
// ---------------------------------------------------------------------------
__global__ __launch_bounds__(256, 2) void qkv_mma_kernel(
    const float* __restrict__ bq, const float* __restrict__ bk, const float* __restrict__ bv)
{
    __shared__ __nv_bfloat16 sAh[128][40], sAl[128][40], sBh[128][40], sBl[128][40];

    const int t    = threadIdx.x;
    const int w    = t >> 5;
    const int lane = t & 31;
    const int g    = lane >> 2;
    const int tc   = lane & 3;
    const int which = blockIdx.z;

    const __nv_bfloat16* Ah = g_xh + (size_t)which * MD;
    const __nv_bfloat16* Al = g_xl + (size_t)which * MD;
    const __nv_bfloat16* Bh = g_wth + (size_t)which * 262144;
    const __nv_bfloat16* Bl = g_wtl + (size_t)which * 262144;
    const float* bias = (which == 0) ? bq : (which == 1) ? bk : bv;
    __nv_bfloat16* outh = (which == 0) ? g_qh : (which == 1) ? g_kh : g_vh;
    __nv_bfloat16* outl = (which == 0) ? g_ql : (which == 1) ? g_kl : g_vl;
    const float scale = (which == 0) ? 0.125f : 1.0f;

    const int row0 = blockIdx.y * 128;
    const int col0 = blockIdx.x * 128;
    const int wm = w & 3, wn = w >> 2;

    const uint32_t sb_ah = smem_u32(sAh), sb_al = smem_u32(sAl);
    const uint32_t sb_bh = smem_u32(sBh), sb_bl = smem_u32(sBl);
    const int brow = lane & 7;
    const int bcol = 8 * ((lane >> 3) & 3);
    const int am15 = lane & 15;
    const int acs  = 8 * (lane >> 4);

    float c[2][8][4];
#pragma unroll
    for (int mi = 0; mi < 2; mi++)
#pragma unroll
        for (int j = 0; j < 8; j++)
#pragma unroll
            for (int k = 0; k < 4; k++) c[mi][j][k] = 0.f;

    for (int kt = 0; kt < 512; kt += 32) {
        __syncthreads();
#pragma unroll
        for (int u = 0; u < 2; u++) {
            const int idx = t + u * 256;
            const int r  = idx >> 2;
            const int c8 = (idx & 3) * 8;
            *(uint4*)&sAh[r][c8] = *(const uint4*)&Ah[(size_t)(row0 + r) * 512 + kt + c8];
            *(uint4*)&sAl[r][c8] = *(const uint4*)&Al[(size_t)(row0 + r) * 512 + kt + c8];
            *(uint4*)&sBh[r][c8] = *(const uint4*)&Bh[(size_t)(col0 + r) * 512 + kt + c8];
            *(uint4*)&sBl[r][c8] = *(const uint4*)&Bl[(size_t)(col0 + r) * 512 + kt + c8];
        }
        __syncthreads();

        uint32_t ah[2][2][4], al[2][2][4];
#pragma unroll
        for (int mi = 0; mi < 2; mi++)
#pragma unroll
            for (int kc = 0; kc < 2; kc++) {
                const uint32_t off =
                    (uint32_t)(((wm * 32 + mi * 16 + am15) * 40 + 16 * kc + acs) * 2);
                ldsm_x4(ah[mi][kc], sb_ah + off);
                ldsm_x4(al[mi][kc], sb_al + off);
            }
#pragma unroll
        for (int j = 0; j < 8; j++) {
            uint32_t bh4[4], bl4[4];
            const uint32_t boff = (uint32_t)(((wn * 64 + 8 * j + brow) * 40 + bcol) * 2);
            ldsm_x4(bh4, sb_bh + boff);
            ldsm_x4(bl4, sb_bl + boff);
#pragma unroll
            for (int mi = 0; mi < 2; mi++)
#pragma unroll
                for (int kc = 0; kc < 2; kc++) {
                    mma_bf16(c[mi][j], ah[mi][kc], bh4[2 * kc], bh4[2 * kc + 1]);
                    mma_bf16(c[mi][j], al[mi][kc], bh4[2 * kc], bh4[2 * kc + 1]);
                    mma_bf16(c[mi][j], ah[mi][kc], bl4[2 * kc], bl4[2 * kc + 1]);
                }
        }
    }

#pragma unroll
    for (int mi = 0; mi < 2; mi++)
#pragma unroll
        for (int rr = 0; rr < 2; rr++) {
            const int m  = row0 + wm * 32 + mi * 16 + g + rr * 8;
            const int bb = m >> 10;
            const int nn = m & 1023;
#pragma unroll
            for (int j = 0; j < 8; j++) {
                const int col = col0 + wn * 64 + 8 * j + 2 * tc;
                const int hh  = col >> 6;
                const int dk  = col & 63;
                const float v0 = (c[mi][j][2 * rr]     + bias[col])     * scale;
                const float v1 = (c[mi][j][2 * rr + 1] + bias[col + 1]) * scale;
                uint32_t hi, lo;
                split_pack(v0, v1, hi, lo);
                const size_t o = ((size_t)(bb * H + hh) * N + nn) * 64 + dk;
                *(uint32_t*)&outh[o] = hi;
                *(uint32_t*)&outl[o] = lo;
            }
        }
}

// ---------------------------------------------------------------------------
// Kernel 2: attention via mma.sync bf16, compensated hi/lo (3-term).
// R11: 128 threads / 64 q-rows per CTA -> 2 CTAs/SM (cross-CTA phase overlap);
// w_g prefetched into registers at iteration start to hide gmem latency.
// ---------------------------------------------------------------------------
__global__ __launch_bounds__(128, 2) void attn_mma_kernel(const float* __restrict__ w_g)
{
    __shared__ __nv_bfloat16 buf[4][64][72];   // 36,864 B

    const int t    = threadIdx.x;
    const int w    = t >> 5;     // 0..3
    const int lane = t & 31;
    const int g    = lane >> 2;
    const int tc   = lane & 3;

    const int qt = blockIdx.x;   // 0..15 (64-row q tiles)
    const int h  = blockIdx.y;
    const int b  = blockIdx.z;
    const size_t bh = (size_t)b * H + h;
    const __nv_bfloat16* qhp = g_qh + (bh * N + (size_t)qt * 64) * 64;
    const __nv_bfloat16* qlp = g_ql + (bh * N + (size_t)qt * 64) * 64;
    const __nv_bfloat16* khp = g_kh + bh * N * 64;
    const __nv_bfloat16* klp = g_kl + bh * N * 64;
    const __nv_bfloat16* vhp = g_vh + bh * N * 64;
    const __nv_bfloat16* vlp = g_vl + bh * N * 64;
    const float* wg = w_g + (bh * N + (size_t)qt * 64) * N;

    const uint32_t sb = smem_u32(buf);

    // ---- stage Q (already prescaled): hi -> buf[0], lo -> buf[2] ([64][72]) ----
    {
        const int r  = t >> 1;            // 0..63
        const int c0 = (t & 1) * 32;
        __nv_bfloat16* qsh = &buf[0][0][0];
        __nv_bfloat16* qsl = &buf[2][0][0];
#pragma unroll
        for (int i = 0; i < 4; i++) {
            *(uint4*)&qsh[r * 72 + c0 + 8 * i] = *(const uint4*)&qhp[r * 64 + c0 + 8 * i];
            *(uint4*)&qsl[r * 72 + c0 + 8 * i] = *(const uint4*)&qlp[r * 64 + c0 + 8 * i];
        }
    }
    __syncthreads();

    // ---- Q A-fragments (4 d-chunks of 16), hi and lo ----
    uint32_t qh[4][4], ql[4][4];
    {
        const int row = w * 16 + (lane & 15);   // 0..63
        const int cs  = 8 * (lane >> 4);
#pragma unroll
        for (int c = 0; c < 4; c++) {
            ldsm_x4(qh[c], sb + (uint32_t)((row * 72 + 16 * c + cs) * 2));
            ldsm_x4(ql[c], sb + (uint32_t)((2 * 64 * 72 + row * 72 + 16 * c + cs) * 2));
        }
    }

    float oc[8][4];
#pragma unroll
    for (int j = 0; j < 8; j++)
#pragma unroll
        for (int k = 0; k < 4; k++) oc[j][k] = 0.f;
    float rs0 = 0.f, rs1 = 0.f;

    const uint32_t kh_b = sb;
    const uint32_t kl_b = sb + 9216u;
    const uint32_t vh_b = sb + 18432u;
    const uint32_t vl_b = sb + 27648u;
    const int brow = lane & 7;
    const int bcol = 8 * ((lane >> 3) & 3);
    const float* w0base = wg + (size_t)(w * 16 + g) * N;
    const float* w1base = w0base + 8 * N;

    for (int kt = 0; kt < 16; kt++) {
        __syncthreads();   // prior readers of buf (Q frags / prev V) done

        // ---- prefetch w_g tile into registers (latency hides under staging+MMA) ----
        float2 wa[8], wb[8];
#pragma unroll
        for (int j = 0; j < 8; j++) {
            const int col = kt * 64 + 8 * j + 2 * tc;
            wa[j] = *(const float2*)&w0base[col];
            wb[j] = *(const float2*)&w1base[col];
        }

        // ---- K tile [key][d] hi/lo ; V tile transposed [d][key] hi/lo ----
        const __nv_bfloat16* kh_t = khp + (size_t)kt * 64 * 64;
        const __nv_bfloat16* kl_t = klp + (size_t)kt * 64 * 64;
        const __nv_bfloat16* vh_t = vhp + (size_t)kt * 64 * 64;
        const __nv_bfloat16* vl_t = vlp + (size_t)kt * 64 * 64;
#pragma unroll
        for (int u = 0; u < 4; u++) {
            const int idx = t + u * 128;       // 0..511
            const int r  = idx >> 3;           // 0..63
            const int c8 = (idx & 7) * 8;      // 0..56
            *(uint4*)&buf[0][r][c8] = *(const uint4*)&kh_t[r * 64 + c8];
            *(uint4*)&buf[1][r][c8] = *(const uint4*)&kl_t[r * 64 + c8];
            const uint4 vh4 = *(const uint4*)&vh_t[r * 64 + c8];
            const uint4 vl4 = *(const uint4*)&vl_t[r * 64 + c8];
            const __nv_bfloat16* va = (const __nv_bfloat16*)&vh4;
            const __nv_bfloat16* vb = (const __nv_bfloat16*)&vl4;
#pragma unroll
            for (int jj = 0; jj < 8; jj++) {
                buf[2][c8 + jj][r] = va[jj];
                buf[3][c8 + jj][r] = vb[jj];
            }
        }
        __syncthreads();

        // ---- S = Qhi*Kh + Qlo*Kh + Qhi*Kl ----
        float sc[8][4];
#pragma unroll
        for (int j = 0; j < 8; j++)
#pragma unroll
            for (int k = 0; k < 4; k++) sc[j][k] = 0.f;
#pragma unroll
        for (int cp = 0; cp < 2; cp++) {
#pragma unroll
            for (int j = 0; j < 8; j++) {
                uint32_t bh4[4], bl4[4];
                const uint32_t off = (uint32_t)(((8 * j + brow) * 72 + 32 * cp + bcol) * 2);
                ldsm_x4(bh4, kh_b + off);
                ldsm_x4(bl4, kl_b + off);
                mma_bf16(sc[j], qh[2 * cp],     bh4[0], bh4[1]);
                mma_bf16(sc[j], ql[2 * cp],     bh4[0], bh4[1]);
                mma_bf16(sc[j], qh[2 * cp],     bl4[0], bl4[1]);
                mma_bf16(sc[j], qh[2 * cp + 1], bh4[2], bh4[3]);
                mma_bf16(sc[j], ql[2 * cp + 1], bh4[2], bh4[3]);
                mma_bf16(sc[j], qh[2 * cp + 1], bl4[2], bl4[3]);
            }
        }

        // ---- P = exp(S - w_g); rowsums; repack to A-fragments hi/lo ----
        uint32_t ph[8][2], pl[8][2];
#pragma unroll
        for (int j = 0; j < 8; j++) {
            const float p0 = __expf(sc[j][0] - wa[j].x);
            const float p1 = __expf(sc[j][1] - wa[j].y);
            const float p2 = __expf(sc[j][2] - wb[j].x);
            const float p3 = __expf(sc[j][3] - wb[j].y);
            rs0 += p0 + p1;
            rs1 += p2 + p3;
            split_pack(p0, p1, ph[j][0], pl[j][0]);
            split_pack(p2, p3, ph[j][1], pl[j][1]);
        }

        // ---- O += Phi*Vh + Plo*Vh + Phi*Vl ----
#pragma unroll
        for (int cp = 0; cp < 2; cp++) {
            const uint32_t ah0[4] = {ph[4*cp][0],   ph[4*cp][1],   ph[4*cp+1][0], ph[4*cp+1][1]};
            const uint32_t ah1[4] = {ph[4*cp+2][0], ph[4*cp+2][1], ph[4*cp+3][0], ph[4*cp+3][1]};
            const uint32_t al0[4] = {pl[4*cp][0],   pl[4*cp][1],   pl[4*cp+1][0], pl[4*cp+1][1]};
            const uint32_t al1[4] = {pl[4*cp+2][0], pl[4*cp+2][1], pl[4*cp+3][0], pl[4*cp+3][1]};
#pragma unroll
            for (int j = 0; j < 8; j++) {
                uint32_t bh4[4], bl4[4];
                const uint32_t off = (uint32_t)(((8 * j + brow) * 72 + 32 * cp + bcol) * 2);
                ldsm_x4(bh4, vh_b + off);
                ldsm_x4(bl4, vl_b + off);
                mma_bf16(oc[j], ah0, bh4[0], bh4[1]);
                mma_bf16(oc[j], al0, bh4[0], bh4[1]);
                mma_bf16(oc[j], ah0, bl4[0], bl4[1]);
                mma_bf16(oc[j], ah1, bh4[2], bh4[3]);
                mma_bf16(oc[j], al1, bh4[2], bh4[3]);
                mma_bf16(oc[j], ah1, bl4[2], bl4[3]);
            }
        }
    }

    // ---- rowsum reduce within quad; write O hi/lo bf16 ----
    rs0 += __shfl_xor_sync(0xffffffffu, rs0, 1);
    rs0 += __shfl_xor_sync(0xffffffffu, rs0, 2);
    rs1 += __shfl_xor_sync(0xffffffffu, rs1, 1);
    rs1 += __shfl_xor_sync(0xffffffffu, rs1, 2);
    const float inv0 = 1.0f / rs0;
    const float inv1 = 1.0f / rs1;

    const size_t r0 = bh * N + (size_t)qt * 64 + w * 16 + g;
#pragma unroll
    for (int j = 0; j < 8; j++) {
        const int col = 8 * j + 2 * tc;
        uint32_t hi0, lo0, hi1, lo1;
        split_pack(oc[j][0] * inv0, oc[j][1] * inv0, hi0, lo0);
        split_pack(oc[j][2] * inv1, oc[j][3] * inv1, hi1, lo1);
        *(uint32_t*)&g_atth[r0 * 64 + col]       = hi0;
        *(uint32_t*)&g_attl[r0 * 64 + col]       = lo0;
        *(uint32_t*)&g_atth[(r0 + 8) * 64 + col] = hi1;
        *(uint32_t*)&g_attl[(r0 + 8) * 64 + col] = lo1;
    }
}

// ---------------------------------------------------------------------------
// Kernel 3: output projection via mma.sync + bias + residual -> g_y fp32.
// A = attention output [b,h,n,dk] bf16 hi/lo; B = Wo^T hi/lo.
// ---------------------------------------------------------------------------
__global__ __launch_bounds__(256, 2) void oproj_mma_kernel(
    const float* __restrict__ bo, const float* __restrict__ residual)
{
    __shared__ __nv_bfloat16 sAh[128][40], sAl[128][40], sBh[128][40], sBl[128][40];

    const int t    = threadIdx.x;
    const int w    = t >> 5;
    const int lane = t & 31;
    const int g    = lane >> 2;
    const int tc   = lane & 3;

    const __nv_bfloat16* Bh = g_wth + 3 * 262144;
    const __nv_bfloat16* Bl = g_wtl + 3 * 262144;

    const int row0 = blockIdx.y * 128;
    const int col0 = blockIdx.x * 128;
    const int wm = w & 3, wn = w >> 2;

    const uint32_t sb_ah = smem_u32(sAh), sb_al = smem_u32(sAl);
    const uint32_t sb_bh = smem_u32(sBh), sb_bl = smem_u32(sBl);
    const int brow = lane & 7;
    const int bcol = 8 * ((lane >> 3) & 3);
    const int am15 = lane & 15;
    const int acs  = 8 * (lane >> 4);

    float c[2][8][4];
#pragma unroll
    for (int mi = 0; mi < 2; mi++)
#pragma unroll
        for (int j = 0; j < 8; j++)
#pragma unroll
            for (int k = 0; k < 4; k++) c[mi][j][k] = 0.f;

    for (int kt = 0; kt < 512; kt += 32) {
        __syncthreads();
#pragma unroll
        for (int u = 0; u < 2; u++) {
            const int idx = t + u * 256;
            const int r  = idx >> 2;
            const int c8 = (idx & 3) * 8;
            const int m  = row0 + r;
            const int bb = m >> 10;
            const int nn = m & 1023;
            const int k0 = kt + c8;
            const size_t a_off = ((size_t)(bb * H + (k0 >> 6)) * N + nn) * 64 + (k0 & 63);
            *(uint4*)&sAh[r][c8] = *(const uint4*)&g_atth[a_off];
            *(uint4*)&sAl[r][c8] = *(const uint4*)&g_attl[a_off];
            *(uint4*)&sBh[r][c8] = *(const uint4*)&Bh[(size_t)(col0 + r) * 512 + kt + c8];
            *(uint4*)&sBl[r][c8] = *(const uint4*)&Bl[(size_t)(col0 + r) * 512 + kt + c8];
        }
        __syncthreads();

        uint32_t ah[2][2][4], al[2][2][4];
#pragma unroll
        for (int mi = 0; mi < 2; mi++)
#pragma unroll
            for (int kc = 0; kc < 2; kc++) {
                const uint32_t off =
                    (uint32_t)(((wm * 32 + mi * 16 + am15) * 40 + 16 * kc + acs) * 2);
                ldsm_x4(ah[mi][kc], sb_ah + off);
                ldsm_x4(al[mi][kc], sb_al + off);
            }
#pragma unroll
        for (int j = 0; j < 8; j++) {
            uint32_t bh4[4], bl4[4];
            const uint32_t boff = (uint32_t)(((wn * 64 + 8 * j + brow) * 40 + bcol) * 2);
            ldsm_x4(bh4, sb_bh + boff);
            ldsm_x4(bl4, sb_bl + boff);
#pragma unroll
            for (int mi = 0; mi < 2; mi++)
#pragma unroll
                for (int kc = 0; kc < 2; kc++) {
                    mma_bf16(c[mi][j], ah[mi][kc], bh4[2 * kc], bh4[2 * kc + 1]);
                    mma_bf16(c[mi][j], al[mi][kc], bh4[2 * kc], bh4[2 * kc + 1]);
                    mma_bf16(c[mi][j], ah[mi][kc], bl4[2 * kc], bl4[2 * kc + 1]);
                }
        }
    }

#pragma unroll
    for (int mi = 0; mi < 2; mi++)
#pragma unroll
        for (int rr = 0; rr < 2; rr++) {
            const int m = row0 + wm * 32 + mi * 16 + g + rr * 8;
#pragma unroll
            for (int j = 0; j < 8; j++) {
                const int col = col0 + wn * 64 + 8 * j + 2 * tc;
                const float2 res = *(const float2*)&residual[(size_t)m * 512 + col];
                float2 o;
                o.x = c[mi][j][2 * rr]     + bo[col]     + res.x;
                o.y = c[mi][j][2 * rr + 1] + bo[col + 1] + res.y;
                *(float2*)&g_y[(size_t)m * 512 + col] = o;
            }
        }
}

// ---------------------------------------------------------------------------
// Kernel 4: LayerNorm (unchanged)
// ---------------------------------------------------------------------------
__global__ __launch_bounds__(128) void ln_kernel(
    const float* __restrict__ gamma, const float* __restrict__ beta,
    float* __restrict__ out)
{
    const int m = blockIdx.x;
    const int t = threadIdx.x;
    const float4 x = *(const float4*)&g_y[(size_t)m * D + t * 4];
    float s  = x.x + x.y + x.z + x.w;
    float ss = x.x * x.x + x.y * x.y + x.z * x.z + x.w * x.w;
#pragma unroll
    for (int o = 16; o > 0; o >>= 1) {
        s  += __shfl_xor_sync(0xffffffffu, s,  o);
        ss += __shfl_xor_sync(0xffffffffu, ss, o);
    }
    __shared__ float red[8];
    const int wid = t >> 5, lane = t & 31;
    if (lane == 0) { red[wid] = s; red[4 + wid] = ss; }
    __syncthreads();
    s  = red[0] + red[1] + red[2] + red[3];
    ss = red[4] + red[5] + red[6] + red[7];
    const float mu  = s * (1.0f / D);
    const float var = ss * (1.0f / D) - mu * mu;
    const float rs  = rsqrtf(var + 1e-5f);
    const float4 g  = *(const float4*)&gamma[t * 4];
    const float4 be = *(const float4*)&beta[t * 4];
    float4 o;
    o.x = (x.x - mu) * rs * g.x + be.x;
    o.y = (x.y - mu) * rs * g.y + be.y;
    o.z = (x.z - mu) * rs * g.z + be.z;
    o.w = (x.w - mu) * rs * g.w + be.w;
    *(float4*)&out[(size_t)m * D + t * 4] = o;
}

// ---------------------------------------------------------------------------
extern "C" void kernel_launch(void* const* d_in, const int* in_sizes, int n_in,
                              void* d_out, int out_size)
{
    (void)in_sizes; (void)n_in; (void)out_size;
    const float* queries = (const float*)d_in[0];
    const float* keys    = (const float*)d_in[1];
    const float* values  = (const float*)d_in[2];
    const float* w_g     = (const float*)d_in[3];
    const float* Wq      = (const float*)d_in[4];
    const float* bq      = (const float*)d_in[5];
    const float* Wk      = (const float*)d_in[6];
    const float* bk      = (const float*)d_in[7];
    const float* Wv      = (const float*)d_in[8];
    const float* bv      = (const float*)d_in[9];
    const float* Wo      = (const float*)d_in[10];
    const float* bo      = (const float*)d_in[11];
    const float* gamma   = (const float*)d_in[12];
    const float* beta    = (const float*)d_in[13];
    float* out = (float*)d_out;

    dim3 gx((unsigned)(MD / 1024), 3);
    convert_x_kernel<<<gx, 256>>>(queries, keys, values);

    dim3 gw(8, 8, 4);
    transpose_w_kernel<<<gw, 256>>>(Wq, Wk, Wv, Wo);

    dim3 gq(HD / 128, M / 128, 3);     // 4 x 64 x 3
    qkv_mma_kernel<<<gq, 256>>>(bq, bk, bv);

    dim3 ga(N / 64, H, B);             // 16 x 8 x 8 = 1024 CTAs
    attn_mma_kernel<<<ga, 128>>>(w_g);

    dim3 go(D / 128, M / 128);         // 4 x 64
    oproj_mma_kernel<<<go, 256>>>(bo, queries);

    ln_kernel<<<M, 128>>>(gamma, beta, out);
}

// round 15
// speedup vs baseline: 1.1842x; 1.1842x over previous
#include <cuda_runtime.h>
#include <cuda_bf16.h>
#include <cstdint>

// Problem constants (fixed by the reference)
namespace cfg {
constexpr int B  = 8;
constexpr int N  = 1024;
constexpr int D  = 512;
constexpr int H  = 8;
constexpr int DK = 64;
constexpr int HD = 512;   // H*DK
constexpr int M  = B * N; // 8192 rows
constexpr size_t MD = (size_t)M * D;
}
using namespace cfg;

// Scratch (no cudaMalloc allowed) — bf16 hi/lo pairs carry the data
__device__ __align__(16) __nv_bfloat16 g_xh[3 * MD];
__device__ __align__(16) __nv_bfloat16 g_xl[3 * MD];
__device__ __align__(16) __nv_bfloat16 g_wth[4 * 512 * 512];  // W^T hi (q,k,v,o)
__device__ __align__(16) __nv_bfloat16 g_wtl[4 * 512 * 512];
__device__ __align__(16) __nv_bfloat16 g_qh[MD], g_ql[MD];    // [b,h,n,dk], prescaled 1/8
__device__ __align__(16) __nv_bfloat16 g_kh[MD], g_kl[MD];
__device__ __align__(16) __nv_bfloat16 g_vh[MD], g_vl[MD];
__device__ __align__(16) __nv_bfloat16 g_atth[MD], g_attl[MD];
__device__ __align__(16) float g_y[MD];

// ===========================================================================
// sm_80-level tensor-core helpers (valid on sm_100 target; validated in R7)
// ===========================================================================
__device__ __forceinline__ uint32_t smem_u32(const void* p) {
    uint32_t a;
    asm("{ .reg .u64 t; cvta.to.shared.u64 t, %1; cvt.u32.u64 %0, t; }" : "=r"(a) : "l"(p));
    return a;
}
__device__ __forceinline__ void ldsm_x4(uint32_t r[4], uint32_t addr) {
    asm volatile("ldmatrix.sync.aligned.m8n8.x4.shared.b16 {%0,%1,%2,%3}, [%4];"
                 : "=r"(r[0]), "=r"(r[1]), "=r"(r[2]), "=r"(r[3]) : "r"(addr));
}
__device__ __forceinline__ void ldsm_x4_trans(uint32_t r[4], uint32_t addr) {
    asm volatile("ldmatrix.sync.aligned.m8n8.x4.trans.shared.b16 {%0,%1,%2,%3}, [%4];"
                 : "=r"(r[0]), "=r"(r[1]), "=r"(r[2]), "=r"(r[3]) : "r"(addr));
}
__device__ __forceinline__ void mma_bf16(float c[4], const uint32_t a[4],
                                         uint32_t b0, uint32_t b1) {
    asm volatile(
        "mma.sync.aligned.m16n8k16.row.col.f32.bf16.bf16.f32 "
        "{%0,%1,%2,%3}, {%4,%5,%6,%7}, {%8,%9}, {%0,%1,%2,%3};"
        : "+f"(c[0]), "+f"(c[1]), "+f"(c[2]), "+f"(c[3])
        : "r"(a[0]), "r"(a[1]), "r"(a[2]), "r"(a[3]), "r"(b0), "r"(b1));
}
// split fp32 pair -> (hi bf16x2, lo bf16x2); element 0 in low half
__device__ __forceinline__ void split_pack(float a, float b, uint32_t& hi, uint32_t& lo) {
    __nv_bfloat16 ah = __float2bfloat16(a);
    __nv_bfloat16 bh = __float2bfloat16(b);
    __nv_bfloat16 al = __float2bfloat16(a - __bfloat162float(ah));
    __nv_bfloat16 bl = __float2bfloat16(b - __bfloat162float(bh));
    __nv_bfloat162 h2(ah, bh), l2(al, bl);
    hi = *(uint32_t*)&h2;
    lo = *(uint32_t*)&l2;
}

// ---------------------------------------------------------------------------
// Prep 1: X (queries/keys/values) fp32 -> hi/lo bf16, elementwise.
// ---------------------------------------------------------------------------
__global__ __launch_bounds__(256) void convert_x_kernel(
    const float* __restrict__ q, const float* __restrict__ k, const float* __restrict__ v)
{
    const int z = blockIdx.y;
    const float* src = (z == 0) ? q : (z == 1) ? k : v;
    const size_t idx = ((size_t)blockIdx.x * 256 + threadIdx.x) * 4;
    const float4 val = *(const float4*)&src[idx];
    uint32_t h0, l0, h1, l1;
    split_pack(val.x, val.y, h0, l0);
    split_pack(val.z, val.w, h1, l1);
    const size_t o = (size_t)z * MD + idx;
    *(uint2*)&g_xh[o] = make_uint2(h0, h1);
    *(uint2*)&g_xl[o] = make_uint2(l0, l1);
}

// ---------------------------------------------------------------------------
// Prep 2: W [k][n] fp32 -> W^T [n][k] hi/lo bf16 (tiled transpose).
// ---------------------------------------------------------------------------
__global__ __launch_bounds__(256) void transpose_w_kernel(
    const float* __restrict__ Wq, const float* __restrict__ Wk,
    const float* __restrict__ Wv, const float* __restrict__ Wo)
{
    __shared__ float tile[64][65];
    const int t = threadIdx.x;
    const int mat = blockIdx.z;
    const float* W = (mat == 0) ? Wq : (mat == 1) ? Wk : (mat == 2) ? Wv : Wo;
    const int r0 = blockIdx.y * 64;   // k block
    const int c0 = blockIdx.x * 64;   // n block
#pragma unroll
    for (int u = 0; u < 16; u++) {
        const int idx = t + u * 256;
        tile[idx >> 6][idx & 63] = W[(size_t)(r0 + (idx >> 6)) * 512 + c0 + (idx & 63)];
    }
    __syncthreads();
#pragma unroll
    for (int u = 0; u < 8; u++) {
        const int idx = t + u * 256;
        const int nl = idx >> 5;
        const int k0 = (idx & 31) * 2;
        uint32_t hi, lo;
        split_pack(tile[k0][nl], tile[k0 + 1][nl], hi, lo);
        const size_t o = (size_t)mat * 262144 + (size_t)(c0 + nl) * 512 + r0 + k0;
        *(uint32_t*)&g_wth[o] = hi;
        *(uint32_t*)&g_wtl[o] = lo;
    }
}

// ---------------------------------------------------------------------------
// Kernel 1: QKV projections via mma.sync, compensated bf16 (3-term).
// 128x128 tile, kstep 32, 8 warps as 4(m) x 2(n); warp tile 32x64.
// Epilogue: +bias (Q also x1/8), split hi/lo, store [b,h,n,dk] bf16.
// ---------------------------------------------------------------------------
__global__ __launch_bounds__(256, 2) void qkv_mma_kernel(
    const float* __restrict__ bq, const float* __restrict__ bk, const float* __restrict__ bv)
{
    __shared__ __nv_bfloat16 sAh[128][40], sAl[128][40], sBh[128][40], sBl[128][40];

    const int t    = threadIdx.x;
    const int w    = t >> 5;
    const int lane = t & 31;
    const int g    = lane >> 2;
    const int tc   = lane & 3;
    const int which = blockIdx.z;

    const __nv_bfloat16* Ah = g_xh + (size_t)which * MD;
    const __nv_bfloat16* Al = g_xl + (size_t)which * MD;
    const __nv_bfloat16* Bh = g_wth + (size_t)which * 262144;
    const __nv_bfloat16* Bl = g_wtl + (size_t)which * 262144;
    const float* bias = (which == 0) ? bq : (which == 1) ? bk : bv;
    __nv_bfloat16* outh = (which == 0) ? g_qh : (which == 1) ? g_kh : g_vh;
    __nv_bfloat16* outl = (which == 0) ? g_ql : (which == 1) ? g_kl : g_vl;
    const float scale = (which == 0) ? 0.125f : 1.0f;

    const int row0 = blockIdx.y * 128;
    const int col0 = blockIdx.x * 128;
    const int wm = w & 3, wn = w >> 2;

    const uint32_t sb_ah = smem_u32(sAh), sb_al = smem_u32(sAl);
    const uint32_t sb_bh = smem_u32(sBh), sb_bl = smem_u32(sBl);
    const int brow = lane & 7;
    const int bcol = 8 * ((lane >> 3) & 3);
    const int am15 = lane & 15;
    const int acs  = 8 * (lane >> 4);

    float c[2][8][4];
#pragma unroll
    for (int mi = 0; mi < 2; mi++)
#pragma unroll
        for (int j = 0; j < 8; j++)
#pragma unroll
            for (int k = 0; k < 4; k++) c[mi][j][k] = 0.f;

    for (int kt = 0; kt < 512; kt += 32) {
        __syncthreads();
#pragma unroll
        for (int u = 0; u < 2; u++) {
            const int idx = t + u * 256;
            const int r  = idx >> 2;
            const int c8 = (idx & 3) * 8;
            *(uint4*)&sAh[r][c8] = *(const uint4*)&Ah[(size_t)(row0 + r) * 512 + kt + c8];
            *(uint4*)&sAl[r][c8] = *(const uint4*)&Al[(size_t)(row0 + r) * 512 + kt + c8];
            *(uint4*)&sBh[r][c8] = *(const uint4*)&Bh[(size_t)(col0 + r) * 512 + kt + c8];
            *(uint4*)&sBl[r][c8] = *(const uint4*)&Bl[(size_t)(col0 + r) * 512 + kt + c8];
        }
        __syncthreads();

        uint32_t ah[2][2][4], al[2][2][4];
#pragma unroll
        for (int mi = 0; mi < 2; mi++)
#pragma unroll
            for (int kc = 0; kc < 2; kc++) {
                const uint32_t off =
                    (uint32_t)(((wm * 32 + mi * 16 + am15) * 40 + 16 * kc + acs) * 2);
                ldsm_x4(ah[mi][kc], sb_ah + off);
                ldsm_x4(al[mi][kc], sb_al + off);
            }
#pragma unroll
        for (int j = 0; j < 8; j++) {
            uint32_t bh4[4], bl4[4];
            const uint32_t boff = (uint32_t)(((wn * 64 + 8 * j + brow) * 40 + bcol) * 2);
            ldsm_x4(bh4, sb_bh + boff);
            ldsm_x4(bl4, sb_bl + boff);
#pragma unroll
            for (int mi = 0; mi < 2; mi++)
#pragma unroll
                for (int kc = 0; kc < 2; kc++) {
                    mma_bf16(c[mi][j], ah[mi][kc], bh4[2 * kc], bh4[2 * kc + 1]);
                    mma_bf16(c[mi][j], al[mi][kc], bh4[2 * kc], bh4[2 * kc + 1]);
                    mma_bf16(c[mi][j], ah[mi][kc], bl4[2 * kc], bl4[2 * kc + 1]);
                }
        }
    }

#pragma unroll
    for (int mi = 0; mi < 2; mi++)
#pragma unroll
        for (int rr = 0; rr < 2; rr++) {
            const int m  = row0 + wm * 32 + mi * 16 + g + rr * 8;
            const int bb = m >> 10;
            const int nn = m & 1023;
#pragma unroll
            for (int j = 0; j < 8; j++) {
                const int col = col0 + wn * 64 + 8 * j + 2 * tc;
                const int hh  = col >> 6;
                const int dk  = col & 63;
                const float v0 = (c[mi][j][2 * rr]     + bias[col])     * scale;
                const float v1 = (c[mi][j][2 * rr + 1] + bias[col + 1]) * scale;
                uint32_t hi, lo;
                split_pack(v0, v1, hi, lo);
                const size_t o = ((size_t)(bb * H + hh) * N + nn) * 64 + dk;
                *(uint32_t*)&outh[o] = hi;
                *(uint32_t*)&outl[o] = lo;
            }
        }
}

// ---------------------------------------------------------------------------
// Kernel 2: attention via mma.sync bf16, compensated hi/lo (3-term).
// R14: back to 256 threads / 128 q-rows (R10 shape). V staged NATURALLY
// (uint4, like K) with a chunk-rotation swizzle (pos = (chunk + row/8) % 9
// over 9x16B chunks per 144B row); O-phase B-frags come from
// ldmatrix.x4.trans — no scalar-store transpose, conflict-free reads.
// w_g prefetched into registers (kept from R11).
// ---------------------------------------------------------------------------
__global__ __launch_bounds__(256, 1) void attn_mma_kernel(const float* __restrict__ w_g)
{
    __shared__ __nv_bfloat16 buf[4][64][72];   // Kh, Kl, Vh(sw), Vl(sw) = 36,864 B

    const int t    = threadIdx.x;
    const int w    = t >> 5;
    const int lane = t & 31;
    const int g    = lane >> 2;
    const int tc   = lane & 3;

    const int qt = blockIdx.x;
    const int h  = blockIdx.y;
    const int b  = blockIdx.z;
    const size_t bh = (size_t)b * H + h;
    const __nv_bfloat16* qhp = g_qh + (bh * N + (size_t)qt * 128) * 64;
    const __nv_bfloat16* qlp = g_ql + (bh * N + (size_t)qt * 128) * 64;
    const __nv_bfloat16* khp = g_kh + bh * N * 64;
    const __nv_bfloat16* klp = g_kl + bh * N * 64;
    const __nv_bfloat16* vhp = g_vh + bh * N * 64;
    const __nv_bfloat16* vlp = g_vl + bh * N * 64;
    const float* wg = w_g + (bh * N + (size_t)qt * 128) * N;

    const uint32_t sb = smem_u32(buf);

    // ---- stage Q (already prescaled): hi -> buf[0..1] [128][72], lo -> buf[2..3] ----
    {
        const int r  = t >> 1;
        const int c0 = (t & 1) * 32;
        __nv_bfloat16* qsh = &buf[0][0][0];
        __nv_bfloat16* qsl = &buf[2][0][0];
#pragma unroll
        for (int i = 0; i < 4; i++) {
            *(uint4*)&qsh[r * 72 + c0 + 8 * i] = *(const uint4*)&qhp[r * 64 + c0 + 8 * i];
            *(uint4*)&qsl[r * 72 + c0 + 8 * i] = *(const uint4*)&qlp[r * 64 + c0 + 8 * i];
        }
    }
    __syncthreads();

    // ---- Q A-fragments (4 d-chunks of 16), hi and lo ----
    uint32_t qh[4][4], ql[4][4];
    {
        const int row = w * 16 + (lane & 15);
        const int cs  = 8 * (lane >> 4);
#pragma unroll
        for (int c = 0; c < 4; c++) {
            ldsm_x4(qh[c], sb + (uint32_t)((row * 72 + 16 * c + cs) * 2));
            ldsm_x4(ql[c], sb + (uint32_t)((2 * 64 * 72 + row * 72 + 16 * c + cs) * 2));
        }
    }

    float oc[8][4];
#pragma unroll
    for (int j = 0; j < 8; j++)
#pragma unroll
        for (int k = 0; k < 4; k++) oc[j][k] = 0.f;
    float rs0 = 0.f, rs1 = 0.f;

    const uint32_t kh_b = sb;
    const uint32_t kl_b = sb + 9216u;
    const uint32_t vh_b = sb + 18432u;
    const uint32_t vl_b = sb + 27648u;
    const int brow = lane & 7;
    const int bcol = 8 * ((lane >> 3) & 3);
    const int vm   = (lane >> 3) & 3;          // trans-ldsm lane-group
    const float* w0base = wg + (size_t)(w * 16 + g) * N;
    const float* w1base = w0base + 8 * N;

    for (int kt = 0; kt < 16; kt++) {
        __syncthreads();   // prior readers of buf (Q frags / prev V) done

        // ---- prefetch w_g tile into registers ----
        float2 wa[8], wb[8];
#pragma unroll
        for (int j = 0; j < 8; j++) {
            const int col = kt * 64 + 8 * j + 2 * tc;
            wa[j] = *(const float2*)&w0base[col];
            wb[j] = *(const float2*)&w1base[col];
        }

        // ---- stage K [key][d] natural; V [key][d] natural + chunk rotation ----
        const __nv_bfloat16* kh_t = khp + (size_t)kt * 64 * 64;
        const __nv_bfloat16* kl_t = klp + (size_t)kt * 64 * 64;
        const __nv_bfloat16* vh_t = vhp + (size_t)kt * 64 * 64;
        const __nv_bfloat16* vl_t = vlp + (size_t)kt * 64 * 64;
#pragma unroll
        for (int u = 0; u < 2; u++) {
            const int idx = t + u * 256;       // 0..511
            const int r   = idx >> 3;          // 0..63
            const int ch  = idx & 7;           // chunk 0..7
            const int c8  = ch * 8;
            *(uint4*)&buf[0][r][c8] = *(const uint4*)&kh_t[r * 64 + c8];
            *(uint4*)&buf[1][r][c8] = *(const uint4*)&kl_t[r * 64 + c8];
            const int pos = (ch + (r >> 3)) % 9;   // rotated chunk position
            *(uint4*)&buf[2][r][pos * 8] = *(const uint4*)&vh_t[r * 64 + c8];
            *(uint4*)&buf[3][r][pos * 8] = *(const uint4*)&vl_t[r * 64 + c8];
        }
        __syncthreads();

        // ---- S = Qhi*Kh + Qlo*Kh + Qhi*Kl ----
        float sc[8][4];
#pragma unroll
        for (int j = 0; j < 8; j++)
#pragma unroll
            for (int k = 0; k < 4; k++) sc[j][k] = 0.f;
#pragma unroll
        for (int cp = 0; cp < 2; cp++) {
#pragma unroll
            for (int j = 0; j < 8; j++) {
                uint32_t bh4[4], bl4[4];
                const uint32_t off = (uint32_t)(((8 * j + brow) * 72 + 32 * cp + bcol) * 2);
                ldsm_x4(bh4, kh_b + off);
                ldsm_x4(bl4, kl_b + off);
                mma_bf16(sc[j], qh[2 * cp],     bh4[0], bh4[1]);
                mma_bf16(sc[j], ql[2 * cp],     bh4[0], bh4[1]);
                mma_bf16(sc[j], qh[2 * cp],     bl4[0], bl4[1]);
                mma_bf16(sc[j], qh[2 * cp + 1], bh4[2], bh4[3]);
                mma_bf16(sc[j], ql[2 * cp + 1], bh4[2], bh4[3]);
                mma_bf16(sc[j], qh[2 * cp + 1], bl4[2], bl4[3]);
            }
        }

        // ---- P = exp(S - w_g); rowsums; repack to A-fragments hi/lo ----
        uint32_t ph[8][2], pl[8][2];
#pragma unroll
        for (int j = 0; j < 8; j++) {
            const float p0 = __expf(sc[j][0] - wa[j].x);
            const float p1 = __expf(sc[j][1] - wa[j].y);
            const float p2 = __expf(sc[j][2] - wb[j].x);
            const float p3 = __expf(sc[j][3] - wb[j].y);
            rs0 += p0 + p1;
            rs1 += p2 + p3;
            split_pack(p0, p1, ph[j][0], pl[j][0]);
            split_pack(p2, p3, ph[j][1], pl[j][1]);
        }

        // ---- O += Phi*Vh + Plo*Vh + Phi*Vl  (B-frags via ldmatrix.trans) ----
#pragma unroll
        for (int cp = 0; cp < 2; cp++) {
            const uint32_t ah0[4] = {ph[4*cp][0],   ph[4*cp][1],   ph[4*cp+1][0], ph[4*cp+1][1]};
            const uint32_t ah1[4] = {ph[4*cp+2][0], ph[4*cp+2][1], ph[4*cp+3][0], ph[4*cp+3][1]};
            const uint32_t al0[4] = {pl[4*cp][0],   pl[4*cp][1],   pl[4*cp+1][0], pl[4*cp+1][1]};
            const uint32_t al1[4] = {pl[4*cp+2][0], pl[4*cp+2][1], pl[4*cp+3][0], pl[4*cp+3][1]};
            const int rowv  = 32 * cp + 8 * vm + brow;   // V key-row for this lane
            const int rbase = 4 * cp + vm;               // rowv >> 3
#pragma unroll
            for (int j = 0; j < 8; j++) {
                const int pos = (j + rbase) % 9;
                const uint32_t off = (uint32_t)((rowv * 72 + pos * 8) * 2);
                uint32_t bh4[4], bl4[4];
                ldsm_x4_trans(bh4, vh_b + off);
                ldsm_x4_trans(bl4, vl_b + off);
                mma_bf16(oc[j], ah0, bh4[0], bh4[1]);
                mma_bf16(oc[j], al0, bh4[0], bh4[1]);
                mma_bf16(oc[j], ah0, bl4[0], bl4[1]);
                mma_bf16(oc[j], ah1, bh4[2], bh4[3]);
                mma_bf16(oc[j], al1, bh4[2], bh4[3]);
                mma_bf16(oc[j], ah1, bl4[2], bl4[3]);
            }
        }
    }

    // ---- rowsum reduce within quad; write O hi/lo bf16 ----
    rs0 += __shfl_xor_sync(0xffffffffu, rs0, 1);
    rs0 += __shfl_xor_sync(0xffffffffu, rs0, 2);
    rs1 += __shfl_xor_sync(0xffffffffu, rs1, 1);
    rs1 += __shfl_xor_sync(0xffffffffu, rs1, 2);
    const float inv0 = 1.0f / rs0;
    const float inv1 = 1.0f / rs1;

    const size_t r0 = bh * N + (size_t)qt * 128 + w * 16 + g;
#pragma unroll
    for (int j = 0; j < 8; j++) {
        const int col = 8 * j + 2 * tc;
        uint32_t hi0, lo0, hi1, lo1;
        split_pack(oc[j][0] * inv0, oc[j][1] * inv0, hi0, lo0);
        split_pack(oc[j][2] * inv1, oc[j][3] * inv1, hi1, lo1);
        *(uint32_t*)&g_atth[r0 * 64 + col]       = hi0;
        *(uint32_t*)&g_attl[r0 * 64 + col]       = lo0;
        *(uint32_t*)&g_atth[(r0 + 8) * 64 + col] = hi1;
        *(uint32_t*)&g_attl[(r0 + 8) * 64 + col] = lo1;
    }
}

// ---------------------------------------------------------------------------
// Kernel 3: output projection via mma.sync + bias + residual -> g_y fp32.
// ---------------------------------------------------------------------------
__global__ __launch_bounds__(256, 2) void oproj_mma_kernel(
    const float* __restrict__ bo, const float* __restrict__ residual)
{
    __shared__ __nv_bfloat16 sAh[128][40], sAl[128][40], sBh[128][40], sBl[128][40];

    const int t    = threadIdx.x;
    const int w    = t >> 5;
    const int lane = t & 31;
    const int g    = lane >> 2;
    const int tc   = lane & 3;

    const __nv_bfloat16* Bh = g_wth + 3 * 262144;
    const __nv_bfloat16* Bl = g_wtl + 3 * 262144;

    const int row0 = blockIdx.y * 128;
    const int col0 = blockIdx.x * 128;
    const int wm = w & 3, wn = w >> 2;

    const uint32_t sb_ah = smem_u32(sAh), sb_al = smem_u32(sAl);
    const uint32_t sb_bh = smem_u32(sBh), sb_bl = smem_u32(sBl);
    const int brow = lane & 7;
    const int bcol = 8 * ((lane >> 3) & 3);
    const int am15 = lane & 15;
    const int acs  = 8 * (lane >> 4);

    float c[2][8][4];
#pragma unroll
    for (int mi = 0; mi < 2; mi++)
#pragma unroll
        for (int j = 0; j < 8; j++)
#pragma unroll
            for (int k = 0; k < 4; k++) c[mi][j][k] = 0.f;

    for (int kt = 0; kt < 512; kt += 32) {
        __syncthreads();
#pragma unroll
        for (int u = 0; u < 2; u++) {
            const int idx = t + u * 256;
            const int r  = idx >> 2;
            const int c8 = (idx & 3) * 8;
            const int m  = row0 + r;
            const int bb = m >> 10;
            const int nn = m & 1023;
            const int k0 = kt + c8;
            const size_t a_off = ((size_t)(bb * H + (k0 >> 6)) * N + nn) * 64 + (k0 & 63);
            *(uint4*)&sAh[r][c8] = *(const uint4*)&g_atth[a_off];
            *(uint4*)&sAl[r][c8] = *(const uint4*)&g_attl[a_off];
            *(uint4*)&sBh[r][c8] = *(const uint4*)&Bh[(size_t)(col0 + r) * 512 + kt + c8];
            *(uint4*)&sBl[r][c8] = *(const uint4*)&Bl[(size_t)(col0 + r) * 512 + kt + c8];
        }
        __syncthreads();

        uint32_t ah[2][2][4], al[2][2][4];
#pragma unroll
        for (int mi = 0; mi < 2; mi++)
#pragma unroll
            for (int kc = 0; kc < 2; kc++) {
                const uint32_t off =
                    (uint32_t)(((wm * 32 + mi * 16 + am15) * 40 + 16 * kc + acs) * 2);
                ldsm_x4(ah[mi][kc], sb_ah + off);
                ldsm_x4(al[mi][kc], sb_al + off);
            }
#pragma unroll
        for (int j = 0; j < 8; j++) {
            uint32_t bh4[4], bl4[4];
            const uint32_t boff = (uint32_t)(((wn * 64 + 8 * j + brow) * 40 + bcol) * 2);
            ldsm_x4(bh4, sb_bh + boff);
            ldsm_x4(bl4, sb_bl + boff);
#pragma unroll
            for (int mi = 0; mi < 2; mi++)
#pragma unroll
                for (int kc = 0; kc < 2; kc++) {
                    mma_bf16(c[mi][j], ah[mi][kc], bh4[2 * kc], bh4[2 * kc + 1]);
                    mma_bf16(c[mi][j], al[mi][kc], bh4[2 * kc], bh4[2 * kc + 1]);
                    mma_bf16(c[mi][j], ah[mi][kc], bl4[2 * kc], bl4[2 * kc + 1]);
                }
        }
    }

#pragma unroll
    for (int mi = 0; mi < 2; mi++)
#pragma unroll
        for (int rr = 0; rr < 2; rr++) {
            const int m = row0 + wm * 32 + mi * 16 + g + rr * 8;
#pragma unroll
            for (int j = 0; j < 8; j++) {
                const int col = col0 + wn * 64 + 8 * j + 2 * tc;
                const float2 res = *(const float2*)&residual[(size_t)m * 512 + col];
                float2 o;
                o.x = c[mi][j][2 * rr]     + bo[col]     + res.x;
                o.y = c[mi][j][2 * rr + 1] + bo[col + 1] + res.y;
                *(float2*)&g_y[(size_t)m * 512 + col] = o;
            }
        }
}

// ---------------------------------------------------------------------------
// Kernel 4: LayerNorm (unchanged)
// ---------------------------------------------------------------------------
__global__ __launch_bounds__(128) void ln_kernel(
    const float* __restrict__ gamma, const float* __restrict__ beta,
    float* __restrict__ out)
{
    const int m = blockIdx.x;
    const int t = threadIdx.x;
    const float4 x = *(const float4*)&g_y[(size_t)m * D + t * 4];
    float s  = x.x + x.y + x.z + x.w;
    float ss = x.x * x.x + x.y * x.y + x.z * x.z + x.w * x.w;
#pragma unroll
    for (int o = 16; o > 0; o >>= 1) {
        s  += __shfl_xor_sync(0xffffffffu, s,  o);
        ss += __shfl_xor_sync(0xffffffffu, ss, o);
    }
    __shared__ float red[8];
    const int wid = t >> 5, lane = t & 31;
    if (lane == 0) { red[wid] = s; red[4 + wid] = ss; }
    __syncthreads();
    s  = red[0] + red[1] + red[2] + red[3];
    ss = red[4] + red[5] + red[6] + red[7];
    const float mu  = s * (1.0f / D);
    const float var = ss * (1.0f / D) - mu * mu;
    const float rs  = rsqrtf(var + 1e-5f);
    const float4 g  = *(const float4*)&gamma[t * 4];
    const float4 be = *(const float4*)&beta[t * 4];
    float4 o;
    o.x = (x.x - mu) * rs * g.x + be.x;
    o.y = (x.y - mu) * rs * g.y + be.y;
    o.z = (x.z - mu) * rs * g.z + be.z;
    o.w = (x.w - mu) * rs * g.w + be.w;
    *(float4*)&out[(size_t)m * D + t * 4] = o;
}

// ---------------------------------------------------------------------------
extern "C" void kernel_launch(void* const* d_in, const int* in_sizes, int n_in,
                              void* d_out, int out_size)
{
    (void)in_sizes; (void)n_in; (void)out_size;
    const float* queries = (const float*)d_in[0];
    const float* keys    = (const float*)d_in[1];
    const float* values  = (const float*)d_in[2];
    const float* w_g     = (const float*)d_in[3];
    const float* Wq      = (const float*)d_in[4];
    const float* bq      = (const float*)d_in[5];
    const float* Wk      = (const float*)d_in[6];
    const float* bk      = (const float*)d_in[7];
    const float* Wv      = (const float*)d_in[8];
    const float* bv      = (const float*)d_in[9];
    const float* Wo      = (const float*)d_in[10];
    const float* bo      = (const float*)d_in[11];
    const float* gamma   = (const float*)d_in[12];
    const float* beta    = (const float*)d_in[13];
    float* out = (float*)d_out;

    dim3 gx((unsigned)(MD / 1024), 3);
    convert_x_kernel<<<gx, 256>>>(queries, keys, values);

    dim3 gw(8, 8, 4);
    transpose_w_kernel<<<gw, 256>>>(Wq, Wk, Wv, Wo);

    dim3 gq(HD / 128, M / 128, 3);     // 4 x 64 x 3
    qkv_mma_kernel<<<gq, 256>>>(bq, bk, bv);

    dim3 ga(N / 128, H, B);            // 8 x 8 x 8 = 512 CTAs
    attn_mma_kernel<<<ga, 256>>>(w_g);

    dim3 go(D / 128, M / 128);         // 4 x 64
    oproj_mma_kernel<<<go, 256>>>(bo, queries);

    ln_kernel<<<M, 128>>>(gamma, beta, out);
}

// round 16
// speedup vs baseline: 1.3528x; 1.1424x over previous
#include <cuda_runtime.h>
#include <cuda_bf16.h>
#include <cstdint>

// Problem constants (fixed by the reference)
namespace cfg {
constexpr int B  = 8;
constexpr int N  = 1024;
constexpr int D  = 512;
constexpr int H  = 8;
constexpr int DK = 64;
constexpr int HD = 512;   // H*DK
constexpr int M  = B * N; // 8192 rows
constexpr size_t MD = (size_t)M * D;
}
using namespace cfg;

// Scratch (no cudaMalloc allowed) — bf16 hi/lo pairs carry the data
__device__ __align__(16) __nv_bfloat16 g_wth[4 * 512 * 512];  // W^T hi (q,k,v,o)
__device__ __align__(16) __nv_bfloat16 g_wtl[4 * 512 * 512];
__device__ __align__(16) __nv_bfloat16 g_qh[MD], g_ql[MD];    // [b,h,n,dk], prescaled 1/8
__device__ __align__(16) __nv_bfloat16 g_kh[MD], g_kl[MD];
__device__ __align__(16) __nv_bfloat16 g_vh[MD], g_vl[MD];
__device__ __align__(16) __nv_bfloat16 g_atth[MD], g_attl[MD];
__device__ __align__(16) float g_y[MD];

// ===========================================================================
// sm_80-level tensor-core helpers (valid on sm_100 target; validated in R7)
// ===========================================================================
__device__ __forceinline__ uint32_t smem_u32(const void* p) {
    uint32_t a;
    asm("{ .reg .u64 t; cvta.to.shared.u64 t, %1; cvt.u32.u64 %0, t; }" : "=r"(a) : "l"(p));
    return a;
}
__device__ __forceinline__ void ldsm_x4(uint32_t r[4], uint32_t addr) {
    asm volatile("ldmatrix.sync.aligned.m8n8.x4.shared.b16 {%0,%1,%2,%3}, [%4];"
                 : "=r"(r[0]), "=r"(r[1]), "=r"(r[2]), "=r"(r[3]) : "r"(addr));
}
__device__ __forceinline__ void ldsm_x4_trans(uint32_t r[4], uint32_t addr) {
    asm volatile("ldmatrix.sync.aligned.m8n8.x4.trans.shared.b16 {%0,%1,%2,%3}, [%4];"
                 : "=r"(r[0]), "=r"(r[1]), "=r"(r[2]), "=r"(r[3]) : "r"(addr));
}
__device__ __forceinline__ void mma_bf16(float c[4], const uint32_t a[4],
                                         uint32_t b0, uint32_t b1) {
    asm volatile(
        "mma.sync.aligned.m16n8k16.row.col.f32.bf16.bf16.f32 "
        "{%0,%1,%2,%3}, {%4,%5,%6,%7}, {%8,%9}, {%0,%1,%2,%3};"
        : "+f"(c[0]), "+f"(c[1]), "+f"(c[2]), "+f"(c[3])
        : "r"(a[0]), "r"(a[1]), "r"(a[2]), "r"(a[3]), "r"(b0), "r"(b1));
}
// split fp32 pair -> (hi bf16x2, lo bf16x2); element 0 in low half
__device__ __forceinline__ void split_pack(float a, float b, uint32_t& hi, uint32_t& lo) {
    __nv_bfloat16 ah = __float2bfloat16(a);
    __nv_bfloat16 bh = __float2bfloat16(b);
    __nv_bfloat16 al = __float2bfloat16(a - __bfloat162float(ah));
    __nv_bfloat16 bl = __float2bfloat16(b - __bfloat162float(bh));
    __nv_bfloat162 h2(ah, bh), l2(al, bl);
    hi = *(uint32_t*)&h2;
    lo = *(uint32_t*)&l2;
}

// ---------------------------------------------------------------------------
// Prep: W [k][n] fp32 -> W^T [n][k] hi/lo bf16 (tiled transpose).
// ---------------------------------------------------------------------------
__global__ __launch_bounds__(256) void transpose_w_kernel(
    const float* __restrict__ Wq, const float* __restrict__ Wk,
    const float* __restrict__ Wv, const float* __restrict__ Wo)
{
    __shared__ float tile[64][65];
    const int t = threadIdx.x;
    const int mat = blockIdx.z;
    const float* W = (mat == 0) ? Wq : (mat == 1) ? Wk : (mat == 2) ? Wv : Wo;
    const int r0 = blockIdx.y * 64;   // k block
    const int c0 = blockIdx.x * 64;   // n block
#pragma unroll
    for (int u = 0; u < 16; u++) {
        const int idx = t + u * 256;
        tile[idx >> 6][idx & 63] = W[(size_t)(r0 + (idx >> 6)) * 512 + c0 + (idx & 63)];
    }
    __syncthreads();
#pragma unroll
    for (int u = 0; u < 8; u++) {
        const int idx = t + u * 256;
        const int nl = idx >> 5;
        const int k0 = (idx & 31) * 2;
        uint32_t hi, lo;
        split_pack(tile[k0][nl], tile[k0 + 1][nl], hi, lo);
        const size_t o = (size_t)mat * 262144 + (size_t)(c0 + nl) * 512 + r0 + k0;
        *(uint32_t*)&g_wth[o] = hi;
        *(uint32_t*)&g_wtl[o] = lo;
    }
}

// ---------------------------------------------------------------------------
// Kernel 1: QKV projections via mma.sync, compensated bf16 (3-term).
// R16: convert fused — A read as fp32 from the original inputs and split
// in registers during staging (convert_x kernel deleted).
// ---------------------------------------------------------------------------
__global__ __launch_bounds__(256, 2) void qkv_mma_kernel(
    const float* __restrict__ Xq, const float* __restrict__ Xk, const float* __restrict__ Xv,
    const float* __restrict__ bq, const float* __restrict__ bk, const float* __restrict__ bv)
{
    __shared__ __nv_bfloat16 sAh[128][40], sAl[128][40], sBh[128][40], sBl[128][40];

    const int t    = threadIdx.x;
    const int w    = t >> 5;
    const int lane = t & 31;
    const int g    = lane >> 2;
    const int tc   = lane & 3;
    const int which = blockIdx.z;

    const float* A = (which == 0) ? Xq : (which == 1) ? Xk : Xv;
    const __nv_bfloat16* Bh = g_wth + (size_t)which * 262144;
    const __nv_bfloat16* Bl = g_wtl + (size_t)which * 262144;
    const float* bias = (which == 0) ? bq : (which == 1) ? bk : bv;
    __nv_bfloat16* outh = (which == 0) ? g_qh : (which == 1) ? g_kh : g_vh;
    __nv_bfloat16* outl = (which == 0) ? g_ql : (which == 1) ? g_kl : g_vl;
    const float scale = (which == 0) ? 0.125f : 1.0f;

    const int row0 = blockIdx.y * 128;
    const int col0 = blockIdx.x * 128;
    const int wm = w & 3, wn = w >> 2;

    const uint32_t sb_ah = smem_u32(sAh), sb_al = smem_u32(sAl);
    const uint32_t sb_bh = smem_u32(sBh), sb_bl = smem_u32(sBl);
    const int brow = lane & 7;
    const int bcol = 8 * ((lane >> 3) & 3);
    const int am15 = lane & 15;
    const int acs  = 8 * (lane >> 4);

    float c[2][8][4];
#pragma unroll
    for (int mi = 0; mi < 2; mi++)
#pragma unroll
        for (int j = 0; j < 8; j++)
#pragma unroll
            for (int k = 0; k < 4; k++) c[mi][j][k] = 0.f;

    for (int kt = 0; kt < 512; kt += 32) {
        __syncthreads();
#pragma unroll
        for (int u = 0; u < 2; u++) {
            const int idx = t + u * 256;
            const int r  = idx >> 2;
            const int c8 = (idx & 3) * 8;
            // A: fp32 -> hi/lo split in registers (convert fused)
            const float4 a0 = *(const float4*)&A[(size_t)(row0 + r) * 512 + kt + c8];
            const float4 a1 = *(const float4*)&A[(size_t)(row0 + r) * 512 + kt + c8 + 4];
            uint32_t h0, l0, h1, l1, h2, l2, h3, l3;
            split_pack(a0.x, a0.y, h0, l0);
            split_pack(a0.z, a0.w, h1, l1);
            split_pack(a1.x, a1.y, h2, l2);
            split_pack(a1.z, a1.w, h3, l3);
            *(uint4*)&sAh[r][c8] = make_uint4(h0, h1, h2, h3);
            *(uint4*)&sAl[r][c8] = make_uint4(l0, l1, l2, l3);
            *(uint4*)&sBh[r][c8] = *(const uint4*)&Bh[(size_t)(col0 + r) * 512 + kt + c8];
            *(uint4*)&sBl[r][c8] = *(const uint4*)&Bl[(size_t)(col0 + r) * 512 + kt + c8];
        }
        __syncthreads();

        uint32_t ah[2][2][4], al[2][2][4];
#pragma unroll
        for (int mi = 0; mi < 2; mi++)
#pragma unroll
            for (int kc = 0; kc < 2; kc++) {
                const uint32_t off =
                    (uint32_t)(((wm * 32 + mi * 16 + am15) * 40 + 16 * kc + acs) * 2);
                ldsm_x4(ah[mi][kc], sb_ah + off);
                ldsm_x4(al[mi][kc], sb_al + off);
            }
#pragma unroll
        for (int j = 0; j < 8; j++) {
            uint32_t bh4[4], bl4[4];
            const uint32_t boff = (uint32_t)(((wn * 64 + 8 * j + brow) * 40 + bcol) * 2);
            ldsm_x4(bh4, sb_bh + boff);
            ldsm_x4(bl4, sb_bl + boff);
#pragma unroll
            for (int mi = 0; mi < 2; mi++)
#pragma unroll
                for (int kc = 0; kc < 2; kc++) {
                    mma_bf16(c[mi][j], ah[mi][kc], bh4[2 * kc], bh4[2 * kc + 1]);
                    mma_bf16(c[mi][j], al[mi][kc], bh4[2 * kc], bh4[2 * kc + 1]);
                    mma_bf16(c[mi][j], ah[mi][kc], bl4[2 * kc], bl4[2 * kc + 1]);
                }
        }
    }

#pragma unroll
    for (int mi = 0; mi < 2; mi++)
#pragma unroll
        for (int rr = 0; rr < 2; rr++) {
            const int m  = row0 + wm * 32 + mi * 16 + g + rr * 8;
            const int bb = m >> 10;
            const int nn = m & 1023;
#pragma unroll
            for (int j = 0; j < 8; j++) {
                const int col = col0 + wn * 64 + 8 * j + 2 * tc;
                const int hh  = col >> 6;
                const int dk  = col & 63;
                const float v0 = (c[mi][j][2 * rr]     + bias[col])     * scale;
                const float v1 = (c[mi][j][2 * rr + 1] + bias[col + 1]) * scale;
                uint32_t hi, lo;
                split_pack(v0, v1, hi, lo);
                const size_t o = ((size_t)(bb * H + hh) * N + nn) * 64 + dk;
                *(uint32_t*)&outh[o] = hi;
                *(uint32_t*)&outl[o] = lo;
            }
        }
}

// ---------------------------------------------------------------------------
// Kernel 2: attention via mma.sync bf16, compensated hi/lo (3-term).
// R16: software pipeline — next K/V tile prefetched into REGISTERS while the
// current tile's S-MMA/exp/O-MMA run; store regs->smem at loop top.
// V chunk-rotation + ldmatrix.trans (R15, validated); w_g register prefetch.
// ---------------------------------------------------------------------------
__global__ __launch_bounds__(256, 1) void attn_mma_kernel(const float* __restrict__ w_g)
{
    __shared__ __nv_bfloat16 buf[4][64][72];   // Kh, Kl, Vh(sw), Vl(sw) = 36,864 B

    const int t    = threadIdx.x;
    const int w    = t >> 5;
    const int lane = t & 31;
    const int g    = lane >> 2;
    const int tc   = lane & 3;

    const int qt = blockIdx.x;
    const int h  = blockIdx.y;
    const int b  = blockIdx.z;
    const size_t bh = (size_t)b * H + h;
    const __nv_bfloat16* qhp = g_qh + (bh * N + (size_t)qt * 128) * 64;
    const __nv_bfloat16* qlp = g_ql + (bh * N + (size_t)qt * 128) * 64;
    const __nv_bfloat16* khp = g_kh + bh * N * 64;
    const __nv_bfloat16* klp = g_kl + bh * N * 64;
    const __nv_bfloat16* vhp = g_vh + bh * N * 64;
    const __nv_bfloat16* vlp = g_vl + bh * N * 64;
    const float* wg = w_g + (bh * N + (size_t)qt * 128) * N;

    const uint32_t sb = smem_u32(buf);

    // ---- stage Q (already prescaled): hi -> buf[0..1] [128][72], lo -> buf[2..3] ----
    {
        const int r  = t >> 1;
        const int c0 = (t & 1) * 32;
        __nv_bfloat16* qsh = &buf[0][0][0];
        __nv_bfloat16* qsl = &buf[2][0][0];
#pragma unroll
        for (int i = 0; i < 4; i++) {
            *(uint4*)&qsh[r * 72 + c0 + 8 * i] = *(const uint4*)&qhp[r * 64 + c0 + 8 * i];
            *(uint4*)&qsl[r * 72 + c0 + 8 * i] = *(const uint4*)&qlp[r * 64 + c0 + 8 * i];
        }
    }
    __syncthreads();

    // ---- Q A-fragments (4 d-chunks of 16), hi and lo ----
    uint32_t qh[4][4], ql[4][4];
    {
        const int row = w * 16 + (lane & 15);
        const int cs  = 8 * (lane >> 4);
#pragma unroll
        for (int c = 0; c < 4; c++) {
            ldsm_x4(qh[c], sb + (uint32_t)((row * 72 + 16 * c + cs) * 2));
            ldsm_x4(ql[c], sb + (uint32_t)((2 * 64 * 72 + row * 72 + 16 * c + cs) * 2));
        }
    }

    float oc[8][4];
#pragma unroll
    for (int j = 0; j < 8; j++)
#pragma unroll
        for (int k = 0; k < 4; k++) oc[j][k] = 0.f;
    float rs0 = 0.f, rs1 = 0.f;

    const uint32_t kh_b = sb;
    const uint32_t kl_b = sb + 9216u;
    const uint32_t vh_b = sb + 18432u;
    const uint32_t vl_b = sb + 27648u;
    const int brow = lane & 7;
    const int bcol = 8 * ((lane >> 3) & 3);
    const int vm   = (lane >> 3) & 3;          // trans-ldsm lane-group
    const float* w0base = wg + (size_t)(w * 16 + g) * N;
    const float* w1base = w0base + 8 * N;

    // per-thread staging coordinates (same for both unroll slots)
    const int sr0 = t >> 3;                   // row for u=0 (0..31)
    const int sr1 = (t + 256) >> 3;           // row for u=1 (32..63)
    const int sch = t & 7;                    // chunk 0..7
    const int sc8 = sch * 8;

    // ---- prefetch tile 0 into registers ----
    uint4 pk_h[2], pk_l[2], pv_h[2], pv_l[2];
    {
        pk_h[0] = *(const uint4*)&khp[sr0 * 64 + sc8];
        pk_l[0] = *(const uint4*)&klp[sr0 * 64 + sc8];
        pv_h[0] = *(const uint4*)&vhp[sr0 * 64 + sc8];
        pv_l[0] = *(const uint4*)&vlp[sr0 * 64 + sc8];
        pk_h[1] = *(const uint4*)&khp[sr1 * 64 + sc8];
        pk_l[1] = *(const uint4*)&klp[sr1 * 64 + sc8];
        pv_h[1] = *(const uint4*)&vhp[sr1 * 64 + sc8];
        pv_l[1] = *(const uint4*)&vlp[sr1 * 64 + sc8];
    }
    const int pos0 = (sch + (sr0 >> 3)) % 9;
    const int pos1 = (sch + (sr1 >> 3)) % 9;

    for (int kt = 0; kt < 16; kt++) {
        __syncthreads();   // prior readers of buf (Q frags / prev V) done

        // ---- store prefetched tile kt: K natural, V rotated ----
        *(uint4*)&buf[0][sr0][sc8]      = pk_h[0];
        *(uint4*)&buf[1][sr0][sc8]      = pk_l[0];
        *(uint4*)&buf[2][sr0][pos0 * 8] = pv_h[0];
        *(uint4*)&buf[3][sr0][pos0 * 8] = pv_l[0];
        *(uint4*)&buf[0][sr1][sc8]      = pk_h[1];
        *(uint4*)&buf[1][sr1][sc8]      = pk_l[1];
        *(uint4*)&buf[2][sr1][pos1 * 8] = pv_h[1];
        *(uint4*)&buf[3][sr1][pos1 * 8] = pv_l[1];
        __syncthreads();

        // ---- issue prefetch of tile kt+1 (latency hidden under MMAs below) ----
        if (kt < 15) {
            const size_t nb = (size_t)(kt + 1) * 64 * 64;
            pk_h[0] = *(const uint4*)&khp[nb + sr0 * 64 + sc8];
            pk_l[0] = *(const uint4*)&klp[nb + sr0 * 64 + sc8];
            pv_h[0] = *(const uint4*)&vhp[nb + sr0 * 64 + sc8];
            pv_l[0] = *(const uint4*)&vlp[nb + sr0 * 64 + sc8];
            pk_h[1] = *(const uint4*)&khp[nb + sr1 * 64 + sc8];
            pk_l[1] = *(const uint4*)&klp[nb + sr1 * 64 + sc8];
            pv_h[1] = *(const uint4*)&vhp[nb + sr1 * 64 + sc8];
            pv_l[1] = *(const uint4*)&vlp[nb + sr1 * 64 + sc8];
        }

        // ---- prefetch w_g tile into registers ----
        float2 wa[8], wb[8];
#pragma unroll
        for (int j = 0; j < 8; j++) {
            const int col = kt * 64 + 8 * j + 2 * tc;
            wa[j] = *(const float2*)&w0base[col];
            wb[j] = *(const float2*)&w1base[col];
        }

        // ---- S = Qhi*Kh + Qlo*Kh + Qhi*Kl ----
        float sc[8][4];
#pragma unroll
        for (int j = 0; j < 8; j++)
#pragma unroll
            for (int k = 0; k < 4; k++) sc[j][k] = 0.f;
#pragma unroll
        for (int cp = 0; cp < 2; cp++) {
#pragma unroll
            for (int j = 0; j < 8; j++) {
                uint32_t bh4[4], bl4[4];
                const uint32_t off = (uint32_t)(((8 * j + brow) * 72 + 32 * cp + bcol) * 2);
                ldsm_x4(bh4, kh_b + off);
                ldsm_x4(bl4, kl_b + off);
                mma_bf16(sc[j], qh[2 * cp],     bh4[0], bh4[1]);
                mma_bf16(sc[j], ql[2 * cp],     bh4[0], bh4[1]);
                mma_bf16(sc[j], qh[2 * cp],     bl4[0], bl4[1]);
                mma_bf16(sc[j], qh[2 * cp + 1], bh4[2], bh4[3]);
                mma_bf16(sc[j], ql[2 * cp + 1], bh4[2], bh4[3]);
                mma_bf16(sc[j], qh[2 * cp + 1], bl4[2], bl4[3]);
            }
        }

        // ---- P = exp(S - w_g); rowsums; repack to A-fragments hi/lo ----
        uint32_t ph[8][2], pl[8][2];
#pragma unroll
        for (int j = 0; j < 8; j++) {
            const float p0 = __expf(sc[j][0] - wa[j].x);
            const float p1 = __expf(sc[j][1] - wa[j].y);
            const float p2 = __expf(sc[j][2] - wb[j].x);
            const float p3 = __expf(sc[j][3] - wb[j].y);
            rs0 += p0 + p1;
            rs1 += p2 + p3;
            split_pack(p0, p1, ph[j][0], pl[j][0]);
            split_pack(p2, p3, ph[j][1], pl[j][1]);
        }

        // ---- O += Phi*Vh + Plo*Vh + Phi*Vl  (B-frags via ldmatrix.trans) ----
#pragma unroll
        for (int cp = 0; cp < 2; cp++) {
            const uint32_t ah0[4] = {ph[4*cp][0],   ph[4*cp][1],   ph[4*cp+1][0], ph[4*cp+1][1]};
            const uint32_t ah1[4] = {ph[4*cp+2][0], ph[4*cp+2][1], ph[4*cp+3][0], ph[4*cp+3][1]};
            const uint32_t al0[4] = {pl[4*cp][0],   pl[4*cp][1],   pl[4*cp+1][0], pl[4*cp+1][1]};
            const uint32_t al1[4] = {pl[4*cp+2][0], pl[4*cp+2][1], pl[4*cp+3][0], pl[4*cp+3][1]};
            const int rowv  = 32 * cp + 8 * vm + brow;   // V key-row for this lane
            const int rbase = 4 * cp + vm;               // rowv >> 3
#pragma unroll
            for (int j = 0; j < 8; j++) {
                const int pos = (j + rbase) % 9;
                const uint32_t off = (uint32_t)((rowv * 72 + pos * 8) * 2);
                uint32_t bh4[4], bl4[4];
                ldsm_x4_trans(bh4, vh_b + off);
                ldsm_x4_trans(bl4, vl_b + off);
                mma_bf16(oc[j], ah0, bh4[0], bh4[1]);
                mma_bf16(oc[j], al0, bh4[0], bh4[1]);
                mma_bf16(oc[j], ah0, bl4[0], bl4[1]);
                mma_bf16(oc[j], ah1, bh4[2], bh4[3]);
                mma_bf16(oc[j], al1, bh4[2], bh4[3]);
                mma_bf16(oc[j], ah1, bl4[2], bl4[3]);
            }
        }
    }

    // ---- rowsum reduce within quad; write O hi/lo bf16 ----
    rs0 += __shfl_xor_sync(0xffffffffu, rs0, 1);
    rs0 += __shfl_xor_sync(0xffffffffu, rs0, 2);
    rs1 += __shfl_xor_sync(0xffffffffu, rs1, 1);
    rs1 += __shfl_xor_sync(0xffffffffu, rs1, 2);
    const float inv0 = 1.0f / rs0;
    const float inv1 = 1.0f / rs1;

    const size_t r0 = bh * N + (size_t)qt * 128 + w * 16 + g;
#pragma unroll
    for (int j = 0; j < 8; j++) {
        const int col = 8 * j + 2 * tc;
        uint32_t hi0, lo0, hi1, lo1;
        split_pack(oc[j][0] * inv0, oc[j][1] * inv0, hi0, lo0);
        split_pack(oc[j][2] * inv1, oc[j][3] * inv1, hi1, lo1);
        *(uint32_t*)&g_atth[r0 * 64 + col]       = hi0;
        *(uint32_t*)&g_attl[r0 * 64 + col]       = lo0;
        *(uint32_t*)&g_atth[(r0 + 8) * 64 + col] = hi1;
        *(uint32_t*)&g_attl[(r0 + 8) * 64 + col] = lo1;
    }
}

// ---------------------------------------------------------------------------
// Kernel 3: output projection via mma.sync + bias + residual -> g_y fp32.
// ---------------------------------------------------------------------------
__global__ __launch_bounds__(256, 2) void oproj_mma_kernel(
    const float* __restrict__ bo, const float* __restrict__ residual)
{
    __shared__ __nv_bfloat16 sAh[128][40], sAl[128][40], sBh[128][40], sBl[128][40];

    const int t    = threadIdx.x;
    const int w    = t >> 5;
    const int lane = t & 31;
    const int g    = lane >> 2;
    const int tc   = lane & 3;

    const __nv_bfloat16* Bh = g_wth + 3 * 262144;
    const __nv_bfloat16* Bl = g_wtl + 3 * 262144;

    const int row0 = blockIdx.y * 128;
    const int col0 = blockIdx.x * 128;
    const int wm = w & 3, wn = w >> 2;

    const uint32_t sb_ah = smem_u32(sAh), sb_al = smem_u32(sAl);
    const uint32_t sb_bh = smem_u32(sBh), sb_bl = smem_u32(sBl);
    const int brow = lane & 7;
    const int bcol = 8 * ((lane >> 3) & 3);
    const int am15 = lane & 15;
    const int acs  = 8 * (lane >> 4);

    float c[2][8][4];
#pragma unroll
    for (int mi = 0; mi < 2; mi++)
#pragma unroll
        for (int j = 0; j < 8; j++)
#pragma unroll
            for (int k = 0; k < 4; k++) c[mi][j][k] = 0.f;

    for (int kt = 0; kt < 512; kt += 32) {
        __syncthreads();
#pragma unroll
        for (int u = 0; u < 2; u++) {
            const int idx = t + u * 256;
            const int r  = idx >> 2;
            const int c8 = (idx & 3) * 8;
            const int m  = row0 + r;
            const int bb = m >> 10;
            const int nn = m & 1023;
            const int k0 = kt + c8;
            const size_t a_off = ((size_t)(bb * H + (k0 >> 6)) * N + nn) * 64 + (k0 & 63);
            *(uint4*)&sAh[r][c8] = *(const uint4*)&g_atth[a_off];
            *(uint4*)&sAl[r][c8] = *(const uint4*)&g_attl[a_off];
            *(uint4*)&sBh[r][c8] = *(const uint4*)&Bh[(size_t)(col0 + r) * 512 + kt + c8];
            *(uint4*)&sBl[r][c8] = *(const uint4*)&Bl[(size_t)(col0 + r) * 512 + kt + c8];
        }
        __syncthreads();

        uint32_t ah[2][2][4], al[2][2][4];
#pragma unroll
        for (int mi = 0; mi < 2; mi++)
#pragma unroll
            for (int kc = 0; kc < 2; kc++) {
                const uint32_t off =
                    (uint32_t)(((wm * 32 + mi * 16 + am15) * 40 + 16 * kc + acs) * 2);
                ldsm_x4(ah[mi][kc], sb_ah + off);
                ldsm_x4(al[mi][kc], sb_al + off);
            }
#pragma unroll
        for (int j = 0; j < 8; j++) {
            uint32_t bh4[4], bl4[4];
            const uint32_t boff = (uint32_t)(((wn * 64 + 8 * j + brow) * 40 + bcol) * 2);
            ldsm_x4(bh4, sb_bh + boff);
            ldsm_x4(bl4, sb_bl + boff);
#pragma unroll
            for (int mi = 0; mi < 2; mi++)
#pragma unroll
                for (int kc = 0; kc < 2; kc++) {
                    mma_bf16(c[mi][j], ah[mi][kc], bh4[2 * kc], bh4[2 * kc + 1]);
                    mma_bf16(c[mi][j], al[mi][kc], bh4[2 * kc], bh4[2 * kc + 1]);
                    mma_bf16(c[mi][j], ah[mi][kc], bl4[2 * kc], bl4[2 * kc + 1]);
                }
        }
    }

#pragma unroll
    for (int mi = 0; mi < 2; mi++)
#pragma unroll
        for (int rr = 0; rr < 2; rr++) {
            const int m = row0 + wm * 32 + mi * 16 + g + rr * 8;
#pragma unroll
            for (int j = 0; j < 8; j++) {
                const int col = col0 + wn * 64 + 8 * j + 2 * tc;
                const float2 res = *(const float2*)&residual[(size_t)m * 512 + col];
                float2 o;
                o.x = c[mi][j][2 * rr]     + bo[col]     + res.x;
                o.y = c[mi][j][2 * rr + 1] + bo[col + 1] + res.y;
                *(float2*)&g_y[(size_t)m * 512 + col] = o;
            }
        }
}

// ---------------------------------------------------------------------------
// Kernel 4: LayerNorm (unchanged)
// ---------------------------------------------------------------------------
__global__ __launch_bounds__(128) void ln_kernel(
    const float* __restrict__ gamma, const float* __restrict__ beta,
    float* __restrict__ out)
{
    const int m = blockIdx.x;
    const int t = threadIdx.x;
    const float4 x = *(const float4*)&g_y[(size_t)m * D + t * 4];
    float s  = x.x + x.y + x.z + x.w;
    float ss = x.x * x.x + x.y * x.y + x.z * x.z + x.w * x.w;
#pragma unroll
    for (int o = 16; o > 0; o >>= 1) {
        s  += __shfl_xor_sync(0xffffffffu, s,  o);
        ss += __shfl_xor_sync(0xffffffffu, ss, o);
    }
    __shared__ float red[8];
    const int wid = t >> 5, lane = t & 31;
    if (lane == 0) { red[wid] = s; red[4 + wid] = ss; }
    __syncthreads();
    s  = red[0] + red[1] + red[2] + red[3];
    ss = red[4] + red[5] + red[6] + red[7];
    const float mu  = s * (1.0f / D);
    const float var = ss * (1.0f / D) - mu * mu;
    const float rs  = rsqrtf(var + 1e-5f);
    const float4 g  = *(const float4*)&gamma[t * 4];
    const float4 be = *(const float4*)&beta[t * 4];
    float4 o;
    o.x = (x.x - mu) * rs * g.x + be.x;
    o.y = (x.y - mu) * rs * g.y + be.y;
    o.z = (x.z - mu) * rs * g.z + be.z;
    o.w = (x.w - mu) * rs * g.w + be.w;
    *(float4*)&out[(size_t)m * D + t * 4] = o;
}

// ---------------------------------------------------------------------------
extern "C" void kernel_launch(void* const* d_in, const int* in_sizes, int n_in,
                              void* d_out, int out_size)
{
    (void)in_sizes; (void)n_in; (void)out_size;
    const float* queries = (const float*)d_in[0];
    const float* keys    = (const float*)d_in[1];
    const float* values  = (const float*)d_in[2];
    const float* w_g     = (const float*)d_in[3];
    const float* Wq      = (const float*)d_in[4];
    const float* bq      = (const float*)d_in[5];
    const float* Wk      = (const float*)d_in[6];
    const float* bk      = (const float*)d_in[7];
    const float* Wv      = (const float*)d_in[8];
    const float* bv      = (const float*)d_in[9];
    const float* Wo      = (const float*)d_in[10];
    const float* bo      = (const float*)d_in[11];
    const float* gamma   = (const float*)d_in[12];
    const float* beta    = (const float*)d_in[13];
    float* out = (float*)d_out;

    dim3 gw(8, 8, 4);
    transpose_w_kernel<<<gw, 256>>>(Wq, Wk, Wv, Wo);

    dim3 gq(HD / 128, M / 128, 3);     // 4 x 64 x 3
    qkv_mma_kernel<<<gq, 256>>>(queries, keys, values, bq, bk, bv);

    dim3 ga(N / 128, H, B);            // 8 x 8 x 8 = 512 CTAs
    attn_mma_kernel<<<ga, 256>>>(w_g);

    dim3 go(D / 128, M / 128);         // 4 x 64
    oproj_mma_kernel<<<go, 256>>>(bo, queries);

    ln_kernel<<<M, 128>>>(gamma, beta, out);
}